// round 16
// baseline (speedup 1.0000x reference)
#include <cuda_runtime.h>
#include <cuda_fp16.h>
#include <cstdint>

// Problem constants
#define TT   512
#define BB   64
#define HID  1024
#define LAY  4
#define NWAVE (TT + LAY - 1)   // 515

// fp32 hidden ring (epilogue z*h term + final output): 2 MB, L2-resident
__device__ float g_ring[2][LAY][BB][HID];

// fp16 activation fragments: [slot][l][bpair 0..31][kc 0..63][tig 0..3] -> uint4
// bpair p: rows ra = (p>>3)*16 + (p&7), rb = ra+8
// uint4 = {ra:k0k1, rb:k0k1, ra:k8k9, rb:k8k9}
__device__ uint4 g_apack16[2][LAY][32][64][4];          // 1 MB

// fp16 x fragments: [t][bpair][kc][tig]
__device__ uint4 g_xpack16[TT][32][64][4];              // 16.8 MB

// fp16 weights: [m=l*2+s][kc][gg][p 0..511][tig] -> uint4
// uint4 = {ra:k0k1, ra:k8k9, rb:k0k1, rb:k8k9}
__device__ uint4 g_wpack16[8ull * 64 * 3 * 512 * 4];    // 50.3 MB

// ---------- helpers ----------
__device__ __forceinline__ uint32_t f2h2(float x, float y) {
    __half2 h = __floats2half2_rn(x, y);
    return *reinterpret_cast<uint32_t*>(&h);
}

__device__ __forceinline__ void mma_fp16(float* c, const uint32_t* a, uint32_t b0, uint32_t b1) {
    asm volatile(
        "mma.sync.aligned.m16n8k16.row.col.f32.f16.f16.f32 "
        "{%0,%1,%2,%3},{%4,%5,%6,%7},{%8,%9},{%0,%1,%2,%3};"
        : "+f"(c[0]), "+f"(c[1]), "+f"(c[2]), "+f"(c[3])
        : "r"(a[0]), "r"(a[1]), "r"(a[2]), "r"(a[3]), "r"(b0), "r"(b1));
}

// ---------- weight packing ----------
__global__ void pack_weights16_kernel(const float* __restrict__ w_ih,
                                      const float* __restrict__ w_hh) {
    int64_t idx = (int64_t)blockIdx.x * blockDim.x + threadIdx.x;
    const int64_t total = 8ll * 64 * 3 * 512 * 4;
    if (idx >= total) return;
    int tig = (int)(idx & 3);
    int64_t t2 = idx >> 2;
    int p  = (int)(t2 & 511);  t2 >>= 9;
    int gg = (int)(t2 % 3);    t2 /= 3;
    int kc = (int)(t2 & 63);
    int m  = (int)(t2 >> 6);
    int l = m >> 1, s = m & 1;
    int ra = gg * HID + (p >> 3) * 16 + (p & 7);
    const float* base = (s ? w_hh : w_ih) + (int64_t)l * 3072 * 1024;
    const float* sa = base + (int64_t)ra * 1024 + kc * 16 + 2 * tig;
    const float* sb = sa + 8 * 1024;
    uint4 q;
    q.x = f2h2(sa[0], sa[1]);
    q.y = f2h2(sa[8], sa[9]);
    q.z = f2h2(sb[0], sb[1]);
    q.w = f2h2(sb[8], sb[9]);
    g_wpack16[idx] = q;
}

// ---------- x packing ----------
__global__ void pack_x16_kernel(const float* __restrict__ x) {
    int64_t idx = (int64_t)blockIdx.x * blockDim.x + threadIdx.x;
    const int64_t total = (int64_t)TT * 32 * 64 * 4;
    if (idx >= total) return;
    int tig   = (int)(idx & 3);
    int kc    = (int)((idx >> 2) & 63);
    int bpair = (int)((idx >> 8) & 31);
    int t     = (int)(idx >> 13);
    int ba = (bpair >> 3) * 16 + (bpair & 7);
    const float* sa = x + ((int64_t)t * BB + ba) * HID + kc * 16 + 2 * tig;
    const float* sb = sa + 8 * HID;
    uint4 q;
    q.x = f2h2(sa[0], sa[1]);
    q.y = f2h2(sb[0], sb[1]);
    q.z = f2h2(sa[8], sa[9]);
    q.w = f2h2(sb[8], sb[9]);
    g_xpack16[t][bpair][kc][tig] = q;
}

// ---------- h0 init: fp32 ring + fp16 fragments ----------
__global__ void init_h0_kernel(const float* __restrict__ h0) {
    int idx = blockIdx.x * blockDim.x + threadIdx.x;   // < L*32*64*4 = 32768
    int tig   = idx & 3;
    int kc    = (idx >> 2) & 63;
    int bpair = (idx >> 8) & 31;
    int l     = idx >> 13;
    int slot = (l + 1) & 1;                            // read-slot of wave l
    int ba = (bpair >> 3) * 16 + (bpair & 7);
    const float* sa = h0 + ((int64_t)l * BB + ba) * HID + kc * 16 + 2 * tig;
    const float* sb = sa + 8 * HID;
    uint4 q;
    q.x = f2h2(sa[0], sa[1]);
    q.y = f2h2(sb[0], sb[1]);
    q.z = f2h2(sa[8], sa[9]);
    q.w = f2h2(sb[8], sb[9]);
    g_apack16[slot][l][bpair][kc][tig] = q;
    float* da = &g_ring[slot][l][ba][kc * 16 + 2 * tig];
    float* db = da + 8 * HID;
    da[0] = sa[0]; da[1] = sa[1]; da[8] = sa[8]; da[9] = sa[9];
    db[0] = sb[0]; db[1] = sb[1]; db[8] = sb[8]; db[9] = sb[9];
}

// ---------- wave kernel ----------
// grid = 128 (l = bx>>5, cb = bx&31), block = 512 (16 warps)
// warp = mstrip(0..3) x ksplit(0..1) x jhalf(0..1)
// merged-phase k-loop: 2 A-loads + 6 B-loads + 12 HMMA per step (8 acc chains).
__global__ void __launch_bounds__(512, 1)
wave_kernel(const float* __restrict__ b_ih,
            const float* __restrict__ b_hh,
            int w) {
    const int l  = blockIdx.x >> 5;
    const int cb = blockIdx.x & 31;
    const int t  = w - l;
    if (t < 0 || t >= TT) return;

    const int rs = (w + 1) & 1;
    const int ws = w & 1;

    const uint4* inp_pack = (l == 0) ? &g_xpack16[t][0][0][0]
                                     : &g_apack16[rs][l - 1][0][0][0];
    const uint4* h_pack = &g_apack16[rs][l][0][0][0];
    const float* hprev  = &g_ring[rs][l][0][0];
    float*       hout   = &g_ring[ws][l][0][0];

    const int lane = threadIdx.x & 31;
    const int warp = threadIdx.x >> 5;
    const int mstrip = warp & 3;
    const int ksplit = (warp >> 2) & 1;
    const int jhalf  = warp >> 3;
    const int gid = lane >> 2;
    const int tig = lane & 3;
    const int c0 = cb * 32;

    const int bpair = mstrip * 8 + gid;
    const int pidx  = cb * 16 + jhalf * 8 + gid;
    const int kc_lo = ksplit * 32;

    // acc[group][jtl][reg]; groups: 0=r, 1=z, 2=gi_n, 3=gh_n
    float acc[4][2][4];
#pragma unroll
    for (int g = 0; g < 4; ++g)
#pragma unroll
        for (int j = 0; j < 2; ++j)
#pragma unroll
            for (int r = 0; r < 4; ++r) acc[g][j][r] = 0.f;

    // ---- merged-phase k-loop ----
    {
        const uint4* paI = inp_pack + (((int64_t)bpair * 64 + kc_lo) << 2) + tig;
        const uint4* paH = h_pack   + (((int64_t)bpair * 64 + kc_lo) << 2) + tig;
        const uint4* pbI = g_wpack16
            + ((((int64_t)(l * 2 + 0) * 64 + kc_lo) * 3) * 512 + pidx) * 4 + tig;
        const uint4* pbH = g_wpack16
            + ((((int64_t)(l * 2 + 1) * 64 + kc_lo) * 3) * 512 + pidx) * 4 + tig;

#pragma unroll 2
        for (int kk = 0; kk < 32; ++kk) {
            uint4 qaI = paI[kk << 2];
            uint4 qaH = paH[kk << 2];
            uint32_t AI[4] = {qaI.x, qaI.y, qaI.z, qaI.w};
            uint32_t AH[4] = {qaH.x, qaH.y, qaH.z, qaH.w};

            const uint4* pbkI = pbI + (int64_t)kk * (3 * 512 * 4);
            const uint4* pbkH = pbH + (int64_t)kk * (3 * 512 * 4);
            uint4 qb0I = pbkI[0];
            uint4 qb1I = pbkI[512 * 4];
            uint4 qb2I = pbkI[2 * 512 * 4];
            uint4 qb0H = pbkH[0];
            uint4 qb1H = pbkH[512 * 4];
            uint4 qb2H = pbkH[2 * 512 * 4];

            // 12 HMMA, same-acc pairs spaced >= 6 issues apart
            mma_fp16(acc[0][0], AI, qb0I.x, qb0I.y);
            mma_fp16(acc[1][0], AI, qb1I.x, qb1I.y);
            mma_fp16(acc[2][0], AI, qb2I.x, qb2I.y);
            mma_fp16(acc[0][1], AI, qb0I.z, qb0I.w);
            mma_fp16(acc[1][1], AI, qb1I.z, qb1I.w);
            mma_fp16(acc[2][1], AI, qb2I.z, qb2I.w);
            mma_fp16(acc[0][0], AH, qb0H.x, qb0H.y);
            mma_fp16(acc[1][0], AH, qb1H.x, qb1H.y);
            mma_fp16(acc[3][0], AH, qb2H.x, qb2H.y);
            mma_fp16(acc[0][1], AH, qb0H.z, qb0H.w);
            mma_fp16(acc[1][1], AH, qb1H.z, qb1H.w);
            mma_fp16(acc[3][1], AH, qb2H.z, qb2H.w);
        }
    }

    // ---- cross-warp K reduction through smem (R6 layout) ----
    __shared__ float red[8][32][32];
    if (ksplit == 1) {
        const float* af = &acc[0][0][0];
        float* dst = &red[jhalf * 4 + mstrip][lane][0];
#pragma unroll
        for (int i = 0; i < 32; ++i) dst[i] = af[i];
    }
    __syncthreads();
    if (ksplit == 1) return;
    {
        float* af = &acc[0][0][0];
        const float* srcr = &red[jhalf * 4 + mstrip][lane][0];
#pragma unroll
        for (int i = 0; i < 32; ++i) af[i] += srcr[i];
    }

    // ---- gates + dual write (exact R6 epilogue) ----
    const float* bi = b_ih + l * 3 * HID;
    const float* bh = b_hh + l * 3 * HID;
    uint32_t frag[4];   // [jtl*2 + half]
#pragma unroll
    for (int jtl = 0; jtl < 2; ++jtl) {
        const int jt = jhalf * 2 + jtl;
        const int jbase = jt * 8 + tig * 2;
#pragma unroll
        for (int half = 0; half < 2; ++half) {
            const int b = mstrip * 16 + gid + half * 8;
            float hnew[2];
#pragma unroll
            for (int par = 0; par < 2; ++par) {
                const int c = c0 + jbase + par;
                const int ri = half * 2 + par;
                float pr  = acc[0][jtl][ri] + bi[c]           + bh[c];
                float pz  = acc[1][jtl][ri] + bi[HID + c]     + bh[HID + c];
                float gin = acc[2][jtl][ri] + bi[2 * HID + c];
                float ghn = acc[3][jtl][ri] + bh[2 * HID + c];
                float rr = 1.f / (1.f + __expf(-pr));
                float zz = 1.f / (1.f + __expf(-pz));
                float nn = tanhf(gin + rr * ghn);
                float hp = hprev[(int64_t)b * HID + c];
                hnew[par] = (1.f - zz) * nn + zz * hp;
                hout[(int64_t)b * HID + c] = hnew[par];
            }
            frag[jtl * 2 + half] = f2h2(hnew[0], hnew[1]);
        }
    }
    {
        uint4 q;
        q.x = frag[0];   // jtl0, half0
        q.y = frag[1];   // jtl0, half1
        q.z = frag[2];   // jtl1, half0
        q.w = frag[3];   // jtl1, half1
        g_apack16[ws][l][bpair][cb * 2 + jhalf][tig] = q;
    }
}

// ---------- output copy ----------
__global__ void copy_out_kernel(float* __restrict__ out) {
    int idx = blockIdx.x * blockDim.x + threadIdx.x;   // < L*B*H
    int l = idx >> 16;
    int rest = idx & 0xFFFF;
    int slot = (TT - 1 + l) & 1;
    out[idx] = (&g_ring[slot][l][0][0])[rest];
}

// ---------- launch ----------
extern "C" void kernel_launch(void* const* d_in, const int* in_sizes, int n_in,
                              void* d_out, int out_size) {
    const float* x    = (const float*)d_in[0];
    const float* h0   = (const float*)d_in[1];
    const float* w_ih = (const float*)d_in[2];
    const float* w_hh = (const float*)d_in[3];
    const float* b_ih = (const float*)d_in[4];
    const float* b_hh = (const float*)d_in[5];
    float* out = (float*)d_out;

    {
        int64_t total = 8ll * 64 * 3 * 512 * 4;
        pack_weights16_kernel<<<(int)((total + 255) / 256), 256>>>(w_ih, w_hh);
    }
    {
        int64_t total = (int64_t)TT * 32 * 64 * 4;
        pack_x16_kernel<<<(int)((total + 255) / 256), 256>>>(x);
    }
    init_h0_kernel<<<(LAY * 32 * 64 * 4) / 256, 256>>>(h0);

    for (int w = 0; w < NWAVE; ++w) {
        wave_kernel<<<128, 512>>>(b_ih, b_hh, w);
    }

    copy_out_kernel<<<(LAY * BB * HID) / 256, 256>>>(out);
}